// round 1
// baseline (speedup 1.0000x reference)
#include <cuda_runtime.h>

typedef unsigned long long ULL;

static __device__ __forceinline__ float mish_f(float x){
    // mish(x) = x * tanh(softplus(x)) = x * ((1+e^x)^2 - 1) / ((1+e^x)^2 + 1)
    float e  = expf(fminf(x, 30.0f));
    float u  = 1.0f + e;
    float u2 = u * u;
    return x * (u2 - 1.0f) / (u2 + 1.0f);
}

// Scratch: A/B precomputed halves of GEMM1 for predicates p1..p3.
// Layout: [pred(3)][half(2)][row(2048)][col(256)]
__device__ float g_AB[6 * 2048 * 256];

// ---------------------------------------------------------------------------
// ab_kernel: A = x @ W1[:128,:], B = x @ W1[128:,:] for each of 3 predicates.
// X: [2048,128], W half: [128,256]. Grid (4 coltiles, 32 rowtiles, 6 mats).
// ---------------------------------------------------------------------------
__global__ __launch_bounds__(256) void ab_kernel(
    const float* __restrict__ emb,
    const float* __restrict__ W1a,
    const float* __restrict__ W1b,
    const float* __restrict__ W1c)
{
    __shared__ float Xs[16][65];
    __shared__ float Ws[16][64];
    int z = blockIdx.z;
    int p = z >> 1, half = z & 1;
    const float* W = (p == 0 ? W1a : (p == 1 ? W1b : W1c)) + half * 128 * 256;
    int row0 = blockIdx.y * 64;
    int col0 = blockIdx.x * 64;
    int tid = threadIdx.x;
    int tr = tid >> 4, tc = tid & 15;
    float acc[4][4];
    #pragma unroll
    for (int r = 0; r < 4; r++)
        #pragma unroll
        for (int c = 0; c < 4; c++) acc[r][c] = 0.0f;

    for (int k0 = 0; k0 < 128; k0 += 16){
        int kx = tid & 15, rx = tid >> 4;
        #pragma unroll
        for (int pp = 0; pp < 4; pp++)
            Xs[kx][rx + pp*16] = emb[(row0 + rx + pp*16)*128 + k0 + kx];
        int cw = tid & 63, kw = tid >> 6;
        #pragma unroll
        for (int pp = 0; pp < 4; pp++)
            Ws[kw + pp*4][cw] = W[(k0 + kw + pp*4)*256 + col0 + cw];
        __syncthreads();
        #pragma unroll
        for (int k = 0; k < 16; k++){
            float a[4], bv[4];
            #pragma unroll
            for (int r = 0; r < 4; r++) a[r] = Xs[k][tr*4 + r];
            #pragma unroll
            for (int c = 0; c < 4; c++) bv[c] = Ws[k][tc*4 + c];
            #pragma unroll
            for (int r = 0; r < 4; r++)
                #pragma unroll
                for (int c = 0; c < 4; c++)
                    acc[r][c] = fmaf(a[r], bv[c], acc[r][c]);
        }
        __syncthreads();
    }
    float* out = g_AB + (size_t)z * 2048 * 256;
    #pragma unroll
    for (int r = 0; r < 4; r++){
        float4 v = make_float4(acc[r][0], acc[r][1], acc[r][2], acc[r][3]);
        *(float4*)&out[(row0 + tr*4 + r)*256 + col0 + tc*4] = v;
    }
}

// ---------------------------------------------------------------------------
// p0_kernel: arity-1 residual MLP. out = x + mish(x@W1+b1)@W2 + b2, d=128.
// 64 rows per block, 32 blocks, 256 threads (8x32 grid, 8x4 microtile).
// ---------------------------------------------------------------------------
__global__ __launch_bounds__(256) void p0_kernel(
    const float* __restrict__ emb,
    const float* __restrict__ W1,
    const float* __restrict__ b1,
    const float* __restrict__ W2,
    const float* __restrict__ b2,
    float* __restrict__ out)
{
    __shared__ float buf[128][65];   // x^T, then h^T : [k][row]
    __shared__ float wch[16][128];
    __shared__ float bias[128];
    int row0 = blockIdx.x * 64;
    int tid = threadIdx.x;
    int tr = tid >> 5, tc = tid & 31;

    for (int idx = tid; idx < 64*128; idx += 256){
        int k = idx & 127, r = idx >> 7;
        buf[k][r] = emb[(row0 + r)*128 + k];
    }
    if (tid < 128) bias[tid] = b1[tid];
    __syncthreads();

    float acc[8][4];
    #pragma unroll
    for (int r = 0; r < 8; r++)
        #pragma unroll
        for (int c = 0; c < 4; c++) acc[r][c] = 0.0f;

    for (int k0 = 0; k0 < 128; k0 += 16){
        #pragma unroll
        for (int pp = 0; pp < 8; pp++){
            int idx = tid + pp*256;
            int c = idx & 127, kk = idx >> 7;
            wch[kk][c] = W1[(k0 + kk)*128 + c];
        }
        __syncthreads();
        #pragma unroll
        for (int k = 0; k < 16; k++){
            float a[8], bv[4];
            #pragma unroll
            for (int r = 0; r < 8; r++) a[r] = buf[k0 + k][tr*8 + r];
            #pragma unroll
            for (int c = 0; c < 4; c++) bv[c] = wch[k][tc*4 + c];
            #pragma unroll
            for (int r = 0; r < 8; r++)
                #pragma unroll
                for (int c = 0; c < 4; c++)
                    acc[r][c] = fmaf(a[r], bv[c], acc[r][c]);
        }
        __syncthreads();
    }

    // h = mish(pre + b1)   (loop above ended with a sync: all buf reads done)
    float hval[8][4];
    #pragma unroll
    for (int r = 0; r < 8; r++)
        #pragma unroll
        for (int c = 0; c < 4; c++)
            hval[r][c] = mish_f(acc[r][c] + bias[tc*4 + c]);
    __syncthreads();   // everyone done reading bias(b1) before overwrite
    #pragma unroll
    for (int r = 0; r < 8; r++)
        #pragma unroll
        for (int c = 0; c < 4; c++)
            buf[tc*4 + c][tr*8 + r] = hval[r][c];
    if (tid < 128) bias[tid] = b2[tid];

    float acc2[8][4];
    #pragma unroll
    for (int r = 0; r < 8; r++)
        #pragma unroll
        for (int c = 0; c < 4; c++) acc2[r][c] = 0.0f;

    for (int k0 = 0; k0 < 128; k0 += 16){
        #pragma unroll
        for (int pp = 0; pp < 8; pp++){
            int idx = tid + pp*256;
            int c = idx & 127, kk = idx >> 7;
            wch[kk][c] = W2[(k0 + kk)*128 + c];
        }
        __syncthreads();
        #pragma unroll
        for (int k = 0; k < 16; k++){
            float a[8], bv[4];
            #pragma unroll
            for (int r = 0; r < 8; r++) a[r] = buf[k0 + k][tr*8 + r];
            #pragma unroll
            for (int c = 0; c < 4; c++) bv[c] = wch[k][tc*4 + c];
            #pragma unroll
            for (int r = 0; r < 8; r++)
                #pragma unroll
                for (int c = 0; c < 4; c++)
                    acc2[r][c] = fmaf(a[r], bv[c], acc2[r][c]);
        }
        __syncthreads();
    }

    #pragma unroll
    for (int r = 0; r < 8; r++){
        int row = row0 + tr*8 + r;
        float4 x = *(const float4*)&emb[row*128 + tc*4];
        float4 o = make_float4(x.x + acc2[r][0] + bias[tc*4+0],
                               x.y + acc2[r][1] + bias[tc*4+1],
                               x.z + acc2[r][2] + bias[tc*4+2],
                               x.w + acc2[r][3] + bias[tc*4+3]);
        *(float4*)&out[row*128 + tc*4] = o;
    }
}

// ---------------------------------------------------------------------------
// pair_kernel: arity-2 predicates. Block = fixed (batch,i), rows j=0..63.
// h[j][k] = mish(A[i][k] + B[j][k] + b1[k]); out = concat(x_i,x_j) + h@W2 + b2.
// 256 threads, 8x32 thread grid, 8x8 microtile, f32x2 packed FMAs.
// ---------------------------------------------------------------------------
__global__ __launch_bounds__(256, 2) void pair_kernel(
    const float* __restrict__ emb,
    const float* __restrict__ b1a, const float* __restrict__ b1b, const float* __restrict__ b1c,
    const float* __restrict__ W2a, const float* __restrict__ W2b, const float* __restrict__ W2c,
    const float* __restrict__ b2a, const float* __restrict__ b2b, const float* __restrict__ b2c,
    float* __restrict__ out)
{
    __shared__ float hs[32][68];    // h^T chunk: [k][j], padded (272B rows, 16B aligned)
    __shared__ float ws[32][256];   // W2 chunk:  [k][c]
    __shared__ float av[256];       // A[i][:] + b1

    int p = blockIdx.y;
    const float* b1 = (p == 0) ? b1a : (p == 1) ? b1b : b1c;
    const float* W2 = (p == 0) ? W2a : (p == 1) ? W2b : W2c;
    const float* b2 = (p == 0) ? b2a : (p == 1) ? b2b : b2c;
    float* outp = out + (size_t)p * 131072 * 256;

    int t = blockIdx.x;            // t = batch*64 + i
    int bidx = t >> 6, i = t & 63;
    const float* Ar = g_AB + ((size_t)(p*2    ) * 2048 + (size_t)(bidx*64 + i)) * 256;
    const float* Bm = g_AB + ((size_t)(p*2 + 1) * 2048 + (size_t)(bidx*64    )) * 256;

    int tid = threadIdx.x;
    int tr = tid >> 5, tc = tid & 31;

    av[tid] = Ar[tid] + b1[tid];

    ULL acc[8][4];
    #pragma unroll
    for (int r = 0; r < 8; r++)
        #pragma unroll
        for (int q = 0; q < 4; q++) acc[r][q] = 0ULL;

    __syncthreads();

    for (int k0 = 0; k0 < 256; k0 += 32){
        // phase A: compute h chunk (64 rows x 32 k-cols), transposed into hs
        #pragma unroll
        for (int it = 0; it < 2; it++){
            int idx = tid + it*256;
            int kk4 = idx & 7, r = idx >> 3;
            float4 v = *(const float4*)&Bm[r*256 + k0 + kk4*4];
            int kb = kk4*4;
            hs[kb+0][r] = mish_f(av[k0+kb+0] + v.x);
            hs[kb+1][r] = mish_f(av[k0+kb+1] + v.y);
            hs[kb+2][r] = mish_f(av[k0+kb+2] + v.z);
            hs[kb+3][r] = mish_f(av[k0+kb+3] + v.w);
        }
        // load W2 chunk [32][256]
        const float4* W2v = (const float4*)(W2 + k0*256);
        #pragma unroll
        for (int it = 0; it < 8; it++){
            int idx = tid + it*256;
            int c4 = idx & 63, kk = idx >> 6;
            *(float4*)&ws[kk][c4*4] = W2v[kk*64 + c4];
        }
        __syncthreads();

        #pragma unroll 8
        for (int k = 0; k < 32; k++){
            float4 a0 = *(const float4*)&hs[k][tr*8];
            float4 a1 = *(const float4*)&hs[k][tr*8 + 4];
            ULL a2[8];
            asm("mov.b64 %0, {%1, %1};" : "=l"(a2[0]) : "f"(a0.x));
            asm("mov.b64 %0, {%1, %1};" : "=l"(a2[1]) : "f"(a0.y));
            asm("mov.b64 %0, {%1, %1};" : "=l"(a2[2]) : "f"(a0.z));
            asm("mov.b64 %0, {%1, %1};" : "=l"(a2[3]) : "f"(a0.w));
            asm("mov.b64 %0, {%1, %1};" : "=l"(a2[4]) : "f"(a1.x));
            asm("mov.b64 %0, {%1, %1};" : "=l"(a2[5]) : "f"(a1.y));
            asm("mov.b64 %0, {%1, %1};" : "=l"(a2[6]) : "f"(a1.z));
            asm("mov.b64 %0, {%1, %1};" : "=l"(a2[7]) : "f"(a1.w));
            const ULL* wsu = (const ULL*)&ws[k][0];
            ULL w0 = wsu[tc*4 + 0];
            ULL w1 = wsu[tc*4 + 1];
            ULL w2 = wsu[tc*4 + 2];
            ULL w3 = wsu[tc*4 + 3];
            #pragma unroll
            for (int rr = 0; rr < 8; rr++){
                asm("fma.rn.f32x2 %0, %1, %2, %0;" : "+l"(acc[rr][0]) : "l"(a2[rr]), "l"(w0));
                asm("fma.rn.f32x2 %0, %1, %2, %0;" : "+l"(acc[rr][1]) : "l"(a2[rr]), "l"(w1));
                asm("fma.rn.f32x2 %0, %1, %2, %0;" : "+l"(acc[rr][2]) : "l"(a2[rr]), "l"(w2));
                asm("fma.rn.f32x2 %0, %1, %2, %0;" : "+l"(acc[rr][3]) : "l"(a2[rr]), "l"(w3));
            }
        }
        __syncthreads();
    }

    // epilogue: residual concat(x_i, x_j) + b2
    int c0 = tc * 8;
    float4 bb0 = *(const float4*)&b2[c0];
    float4 bb1 = *(const float4*)&b2[c0 + 4];
    const float* xi = emb + (size_t)(bidx*64 + i) * 128;
    float4 xi0, xi1;
    if (c0 < 128){
        xi0 = *(const float4*)&xi[c0];
        xi1 = *(const float4*)&xi[c0 + 4];
    }
    #pragma unroll
    for (int rr = 0; rr < 8; rr++){
        int j = tr*8 + rr;
        float v[8];
        asm("mov.b64 {%0, %1}, %2;" : "=f"(v[0]), "=f"(v[1]) : "l"(acc[rr][0]));
        asm("mov.b64 {%0, %1}, %2;" : "=f"(v[2]), "=f"(v[3]) : "l"(acc[rr][1]));
        asm("mov.b64 {%0, %1}, %2;" : "=f"(v[4]), "=f"(v[5]) : "l"(acc[rr][2]));
        asm("mov.b64 {%0, %1}, %2;" : "=f"(v[6]), "=f"(v[7]) : "l"(acc[rr][3]));
        float4 r0, r1;
        if (c0 < 128){
            r0 = xi0; r1 = xi1;
        } else {
            const float* xj = emb + (size_t)(bidx*64 + j) * 128 + (c0 - 128);
            r0 = *(const float4*)&xj[0];
            r1 = *(const float4*)&xj[4];
        }
        size_t row = (size_t)t * 64 + j;
        float* o = outp + row * 256 + c0;
        float4 o0 = make_float4(r0.x + v[0] + bb0.x, r0.y + v[1] + bb0.y,
                                r0.z + v[2] + bb0.z, r0.w + v[3] + bb0.w);
        float4 o1 = make_float4(r1.x + v[4] + bb1.x, r1.y + v[5] + bb1.y,
                                r1.z + v[6] + bb1.z, r1.w + v[7] + bb1.w);
        *(float4*)&o[0] = o0;
        *(float4*)&o[4] = o1;
    }
}

// ---------------------------------------------------------------------------
extern "C" void kernel_launch(void* const* d_in, const int* in_sizes, int n_in,
                              void* d_out, int out_size)
{
    (void)in_sizes; (void)n_in; (void)out_size;
    const float* emb  = (const float*)d_in[0];
    const float* W1_0 = (const float*)d_in[2];
    const float* b1_0 = (const float*)d_in[3];
    const float* W2_0 = (const float*)d_in[4];
    const float* b2_0 = (const float*)d_in[5];
    const float* W1_1 = (const float*)d_in[6];
    const float* b1_1 = (const float*)d_in[7];
    const float* W2_1 = (const float*)d_in[8];
    const float* b2_1 = (const float*)d_in[9];
    const float* W1_2 = (const float*)d_in[10];
    const float* b1_2 = (const float*)d_in[11];
    const float* W2_2 = (const float*)d_in[12];
    const float* b2_2 = (const float*)d_in[13];
    const float* W1_3 = (const float*)d_in[14];
    const float* b1_3 = (const float*)d_in[15];
    const float* W2_3 = (const float*)d_in[16];
    const float* b2_3 = (const float*)d_in[17];
    float* out = (float*)d_out;

    ab_kernel<<<dim3(4, 32, 6), 256>>>(emb, W1_1, W1_2, W1_3);
    p0_kernel<<<32, 256>>>(emb, W1_0, b1_0, W2_0, b2_0, out);
    pair_kernel<<<dim3(2048, 3), 256>>>(emb,
                                        b1_1, b1_2, b1_3,
                                        W2_1, W2_2, W2_3,
                                        b2_1, b2_2, b2_3,
                                        out + 262144);
}

// round 3
// speedup vs baseline: 1.8995x; 1.8995x over previous
#include <cuda_runtime.h>

typedef unsigned int U32;
typedef unsigned long long ULL;

static __device__ __forceinline__ float mish_f(float x){
    // mish(x) = x * ((1+e^x)^2 - 1) / ((1+e^x)^2 + 1)
    float e  = __expf(fminf(x, 30.0f));
    float u  = 1.0f + e;
    float u2 = u * u;
    return x * __fdividef(u2 - 1.0f, u2 + 1.0f);
}

// g_AB: [pred(3)][half(2)][row(2048)][col(256)]  (P = x@W1_top, Q = x@W1_bot)
__device__ float g_AB[6 * 2048 * 256];
// g_W2f: W2 per pred, tf32-converted, pre-laid-out in m16n8k8 B-fragment order:
// [pred(3)][chunk(4)][ks(8)][nt(32)][lane(32)][comp(2)]
__device__ U32 g_W2f[3 * 65536];

// ---------------------------------------------------------------------------
// w2frag_kernel: W2 -> tf32 fragment layout.
// ---------------------------------------------------------------------------
__global__ __launch_bounds__(256) void w2frag_kernel(
    const float* __restrict__ W2a,
    const float* __restrict__ W2b,
    const float* __restrict__ W2c)
{
    int idx = blockIdx.x * 256 + threadIdx.x;   // 0 .. 196607
    int p = idx >> 16;
    int rem = idx & 65535;
    int k = rem >> 8, n = rem & 255;
    const float* W2 = (p == 0) ? W2a : (p == 1) ? W2b : W2c;
    float v = W2[k * 256 + n];
    U32 tv;
    asm("cvt.rna.tf32.f32 %0, %1;" : "=r"(tv) : "f"(v));
    int c = k >> 6, kk = k & 63;
    int ks = kk >> 3, tl = kk & 3, khi = (kk >> 2) & 1;
    int lane = (n & 7) * 4 + tl, nt = n >> 3;
    g_W2f[p * 65536 + c * 16384 + ks * 2048 + nt * 64 + lane * 2 + khi] = tv;
}

// ---------------------------------------------------------------------------
// ab_kernel: P = x @ W1[:128,:], Q = x @ W1[128:,:] for each of 3 predicates.
// ---------------------------------------------------------------------------
__global__ __launch_bounds__(256) void ab_kernel(
    const float* __restrict__ emb,
    const float* __restrict__ W1a,
    const float* __restrict__ W1b,
    const float* __restrict__ W1c)
{
    __shared__ float Xs[16][65];
    __shared__ float Ws[16][64];
    int z = blockIdx.z;
    int p = z >> 1, half = z & 1;
    const float* W = (p == 0 ? W1a : (p == 1 ? W1b : W1c)) + half * 128 * 256;
    int row0 = blockIdx.y * 64;
    int col0 = blockIdx.x * 64;
    int tid = threadIdx.x;
    int tr = tid >> 4, tc = tid & 15;
    float acc[4][4];
    #pragma unroll
    for (int r = 0; r < 4; r++)
        #pragma unroll
        for (int c = 0; c < 4; c++) acc[r][c] = 0.0f;

    for (int k0 = 0; k0 < 128; k0 += 16){
        int kx = tid & 15, rx = tid >> 4;
        #pragma unroll
        for (int pp = 0; pp < 4; pp++)
            Xs[kx][rx + pp*16] = emb[(row0 + rx + pp*16)*128 + k0 + kx];
        int cw = tid & 63, kw = tid >> 6;
        #pragma unroll
        for (int pp = 0; pp < 4; pp++)
            Ws[kw + pp*4][cw] = W[(k0 + kw + pp*4)*256 + col0 + cw];
        __syncthreads();
        #pragma unroll
        for (int k = 0; k < 16; k++){
            float a[4], bv[4];
            #pragma unroll
            for (int r = 0; r < 4; r++) a[r] = Xs[k][tr*4 + r];
            #pragma unroll
            for (int c = 0; c < 4; c++) bv[c] = Ws[k][tc*4 + c];
            #pragma unroll
            for (int r = 0; r < 4; r++)
                #pragma unroll
                for (int c = 0; c < 4; c++)
                    acc[r][c] = fmaf(a[r], bv[c], acc[r][c]);
        }
        __syncthreads();
    }
    float* out = g_AB + (size_t)z * 2048 * 256;
    #pragma unroll
    for (int r = 0; r < 4; r++){
        float4 v = make_float4(acc[r][0], acc[r][1], acc[r][2], acc[r][3]);
        *(float4*)&out[(row0 + tr*4 + r)*256 + col0 + tc*4] = v;
    }
}

// ---------------------------------------------------------------------------
// p0_kernel: arity-1 residual MLP.
// ---------------------------------------------------------------------------
__global__ __launch_bounds__(256) void p0_kernel(
    const float* __restrict__ emb,
    const float* __restrict__ W1,
    const float* __restrict__ b1,
    const float* __restrict__ W2,
    const float* __restrict__ b2,
    float* __restrict__ out)
{
    __shared__ float buf[128][65];
    __shared__ float wch[16][128];
    __shared__ float bias[128];
    int row0 = blockIdx.x * 64;
    int tid = threadIdx.x;
    int tr = tid >> 5, tc = tid & 31;

    for (int idx = tid; idx < 64*128; idx += 256){
        int k = idx & 127, r = idx >> 7;
        buf[k][r] = emb[(row0 + r)*128 + k];
    }
    if (tid < 128) bias[tid] = b1[tid];
    __syncthreads();

    float acc[8][4];
    #pragma unroll
    for (int r = 0; r < 8; r++)
        #pragma unroll
        for (int c = 0; c < 4; c++) acc[r][c] = 0.0f;

    for (int k0 = 0; k0 < 128; k0 += 16){
        #pragma unroll
        for (int pp = 0; pp < 8; pp++){
            int idx = tid + pp*256;
            int c = idx & 127, kk = idx >> 7;
            wch[kk][c] = W1[(k0 + kk)*128 + c];
        }
        __syncthreads();
        #pragma unroll
        for (int k = 0; k < 16; k++){
            float a[8], bv[4];
            #pragma unroll
            for (int r = 0; r < 8; r++) a[r] = buf[k0 + k][tr*8 + r];
            #pragma unroll
            for (int c = 0; c < 4; c++) bv[c] = wch[k][tc*4 + c];
            #pragma unroll
            for (int r = 0; r < 8; r++)
                #pragma unroll
                for (int c = 0; c < 4; c++)
                    acc[r][c] = fmaf(a[r], bv[c], acc[r][c]);
        }
        __syncthreads();
    }

    float hval[8][4];
    #pragma unroll
    for (int r = 0; r < 8; r++)
        #pragma unroll
        for (int c = 0; c < 4; c++)
            hval[r][c] = mish_f(acc[r][c] + bias[tc*4 + c]);
    __syncthreads();
    #pragma unroll
    for (int r = 0; r < 8; r++)
        #pragma unroll
        for (int c = 0; c < 4; c++)
            buf[tc*4 + c][tr*8 + r] = hval[r][c];
    if (tid < 128) bias[tid] = b2[tid];

    float acc2[8][4];
    #pragma unroll
    for (int r = 0; r < 8; r++)
        #pragma unroll
        for (int c = 0; c < 4; c++) acc2[r][c] = 0.0f;

    for (int k0 = 0; k0 < 128; k0 += 16){
        #pragma unroll
        for (int pp = 0; pp < 8; pp++){
            int idx = tid + pp*256;
            int c = idx & 127, kk = idx >> 7;
            wch[kk][c] = W2[(k0 + kk)*128 + c];
        }
        __syncthreads();
        #pragma unroll
        for (int k = 0; k < 16; k++){
            float a[8], bv[4];
            #pragma unroll
            for (int r = 0; r < 8; r++) a[r] = buf[k0 + k][tr*8 + r];
            #pragma unroll
            for (int c = 0; c < 4; c++) bv[c] = wch[k][tc*4 + c];
            #pragma unroll
            for (int r = 0; r < 8; r++)
                #pragma unroll
                for (int c = 0; c < 4; c++)
                    acc2[r][c] = fmaf(a[r], bv[c], acc2[r][c]);
        }
        __syncthreads();
    }

    #pragma unroll
    for (int r = 0; r < 8; r++){
        int row = row0 + tr*8 + r;
        float4 x = *(const float4*)&emb[row*128 + tc*4];
        float4 o = make_float4(x.x + acc2[r][0] + bias[tc*4+0],
                               x.y + acc2[r][1] + bias[tc*4+1],
                               x.z + acc2[r][2] + bias[tc*4+2],
                               x.w + acc2[r][3] + bias[tc*4+3]);
        *(float4*)&out[row*128 + tc*4] = o;
    }
}

// ---------------------------------------------------------------------------
// pair_mma_kernel: arity-2 predicates via tf32 mma.sync (m16n8k8).
// Block = (pred p, batch b, i-pair q): 512 threads, 16 warps (4M x 4N).
// GEMM: M=128 (rows r = isel*64 + j), N=256, K=256 in 4 chunks of 64.
// h[r][k] = mish(P[i][k] + Q[j][k] + b1[k]);  D = h @ W2;  out = concat+D+b2.
// SMEM (floats): buf0 A[0,8192) B[8192,24576); buf1 A[24576,32768)
//   B[32768,49152); av[49152,49664).
// ---------------------------------------------------------------------------
#define PAIR_SMEM_BYTES (49664 * 4)

#define MMA_TF32(d, a, b) \
    asm volatile("mma.sync.aligned.m16n8k8.row.col.f32.tf32.tf32.f32 " \
        "{%0,%1,%2,%3}, {%4,%5,%6,%7}, {%8,%9}, {%0,%1,%2,%3};" \
        : "+f"(d[0]), "+f"(d[1]), "+f"(d[2]), "+f"(d[3]) \
        : "r"((a).x), "r"((a).y), "r"((a).z), "r"((a).w), \
          "r"((b).x), "r"((b).y))

__global__ __launch_bounds__(512, 1) void pair_mma_kernel(
    const float* __restrict__ emb,
    const float* __restrict__ b1a, const float* __restrict__ b1b, const float* __restrict__ b1c,
    const float* __restrict__ b2a, const float* __restrict__ b2b, const float* __restrict__ b2c,
    float* __restrict__ outbase)
{
    extern __shared__ float sm[];
    float* av = sm + 49152;

    int p = blockIdx.y;
    const float* b1 = (p == 0) ? b1a : (p == 1) ? b1b : b1c;
    const float* b2 = (p == 0) ? b2a : (p == 1) ? b2b : b2c;
    const U32* W2f = g_W2f + p * 65536;
    float* outp = outbase + (size_t)p * 33554432;

    int bx = blockIdx.x;
    int b = bx >> 5, q = bx & 31;
    const float* Pi0 = g_AB + ((size_t)(p*2) * 2048 + (size_t)(b*64 + 2*q)) * 256;
    const float* Q   = g_AB + ((size_t)(p*2 + 1) * 2048 + (size_t)(b*64)) * 256;

    int t = threadIdx.x;
    int wid = t >> 5, lane = t & 31;
    int wm = wid & 3, wn = wid >> 2;
    int g = lane >> 2, tl = lane & 3;

    // av[isel][k] = P[i][k] + b1[k]
    if (t < 256) av[t] = Pi0[t] + b1[t];
    else         av[t] = Pi0[t] + b1[t - 256];   // Pi1 row is contiguous after Pi0
    __syncthreads();

    // producer: fills A (h tile, fragment layout, XOR swizzled) + B (W2 copy)
    int pj = t >> 3;            // 0..63 : j row
    int pks = t & 7;            // 0..7  : k slot (8 k's)
    auto produce = [&](int c, float* Ab, U32* Bb){
        const float* Qr = Q + (size_t)pj * 256 + c*64 + pks*8;
        float4 q0 = *(const float4*)Qr;
        float4 q1 = *(const float4*)(Qr + 4);
        float qv[8] = {q0.x,q0.y,q0.z,q0.w,q1.x,q1.y,q1.z,q1.w};
        int kb = c*64 + pks*8;
        U32* Au = (U32*)Ab;
        #pragma unroll
        for (int isel = 0; isel < 2; isel++){
            const float* avp = av + isel*256 + kb;
            int r = isel*64 + pj;
            int mt = r >> 4, gg = r & 7, hi = (r >> 3) & 1;
            U32* base = Au + pks*1024 + mt*128;
            #pragma unroll
            for (int kk = 0; kk < 8; kk++){
                int tll = kk & 3, khi = kk >> 2;
                float hv = mish_f(avp[kk] + qv[kk]);
                U32 tv;
                asm("cvt.rna.tf32.f32 %0, %1;" : "=r"(tv) : "f"(hv));
                int lane_s = (gg*4 + tll) ^ (pks << 2);
                base[lane_s*4 + ((khi << 1) | hi)] = tv;
            }
        }
        const uint4* src = (const uint4*)(W2f + c*16384);
        uint4* dst = (uint4*)Bb;
        #pragma unroll
        for (int i = 0; i < 8; i++)
            dst[t + i*512] = src[t + i*512];
    };

    float acc[2][8][4];
    #pragma unroll
    for (int mf = 0; mf < 2; mf++)
        #pragma unroll
        for (int nf = 0; nf < 8; nf++)
            #pragma unroll
            for (int u = 0; u < 4; u++) acc[mf][nf][u] = 0.0f;

    auto consume = [&](float* Ab, U32* Bb){
        U32* Au = (U32*)Ab;
        #pragma unroll
        for (int ks = 0; ks < 8; ks++){
            int lsw = (lane ^ (ks << 2)) & 31;
            uint4 a0 = *(uint4*)(Au + ks*1024 + (wm*2    )*128 + lsw*4);
            uint4 a1 = *(uint4*)(Au + ks*1024 + (wm*2 + 1)*128 + lsw*4);
            uint2 bf[8];
            #pragma unroll
            for (int nf = 0; nf < 8; nf++)
                bf[nf] = *(uint2*)(Bb + ks*2048 + (wn*8 + nf)*64 + lane*2);
            #pragma unroll
            for (int nf = 0; nf < 8; nf++){
                MMA_TF32(acc[0][nf], a0, bf[nf]);
                MMA_TF32(acc[1][nf], a1, bf[nf]);
            }
        }
    };

    float* A0 = sm;          U32* B0 = (U32*)(sm + 8192);
    float* A1 = sm + 24576;  U32* B1 = (U32*)(sm + 32768);

    produce(0, A0, B0);
    __syncthreads();
    produce(1, A1, B1);
    consume(A0, B0);
    __syncthreads();
    produce(2, A0, B0);
    consume(A1, B1);
    __syncthreads();
    produce(3, A1, B1);
    consume(A0, B0);
    __syncthreads();
    consume(A1, B1);
    __syncthreads();

    // ---- epilogue staging: xi0/xi1/b2 -> A0 region, xj -> B0 region ----
    float* xi_s = sm;            // [2][128]
    float* b2_s = sm + 256;      // [256]
    float* xj_s = sm + 8192;     // [64][132]
    const float* embB = emb + (size_t)(b*64) * 128;

    if (t < 32){
        float4 v = ((const float4*)(embB + (size_t)(2*q)*128))[t];
        *(float4*)&xi_s[t*4] = v;
    } else if (t < 64){
        int t2 = t - 32;
        float4 v = ((const float4*)(embB + (size_t)(2*q + 1)*128))[t2];
        *(float4*)&xi_s[128 + t2*4] = v;
    } else if (t < 128){
        int t2 = t - 64;
        float4 v = ((const float4*)b2)[t2];
        *(float4*)&b2_s[t2*4] = v;
    }
    {
        int jr = t >> 3, seg = t & 7;
        const float4* s = (const float4*)(embB + (size_t)jr*128 + seg*16);
        float4 v0 = s[0], v1 = s[1], v2 = s[2], v3 = s[3];
        float4* d = (float4*)&xj_s[jr*132 + seg*16];
        d[0] = v0; d[1] = v1; d[2] = v2; d[3] = v3;
    }
    __syncthreads();

    int isel = wm >> 1;
    int i = 2*q + isel;
    const float* xiw = xi_s + isel*128;
    size_t rowbase = (size_t)(b*64 + i) * 64;

    #pragma unroll
    for (int mf = 0; mf < 2; mf++){
        int jr0 = (wm & 1)*32 + mf*16 + g;
        int jr1 = jr0 + 8;
        float* o0 = outp + (rowbase + jr0) * 256;
        float* o1 = outp + (rowbase + jr1) * 256;
        #pragma unroll
        for (int nf = 0; nf < 8; nf++){
            int col = wn*64 + nf*8 + 2*tl;
            float add00, add01, add10, add11;
            if (wn < 2){
                float x0 = xiw[col], x1 = xiw[col + 1];
                add00 = x0; add01 = x1; add10 = x0; add11 = x1;
            } else {
                int cc = col - 128;
                add00 = xj_s[jr0*132 + cc];
                add01 = xj_s[jr0*132 + cc + 1];
                add10 = xj_s[jr1*132 + cc];
                add11 = xj_s[jr1*132 + cc + 1];
            }
            float bb0 = b2_s[col], bb1 = b2_s[col + 1];
            float2 v0 = make_float2(acc[mf][nf][0] + add00 + bb0,
                                    acc[mf][nf][1] + add01 + bb1);
            float2 v1 = make_float2(acc[mf][nf][2] + add10 + bb0,
                                    acc[mf][nf][3] + add11 + bb1);
            *(float2*)&o0[col] = v0;
            *(float2*)&o1[col] = v1;
        }
    }
}

// ---------------------------------------------------------------------------
extern "C" void kernel_launch(void* const* d_in, const int* in_sizes, int n_in,
                              void* d_out, int out_size)
{
    (void)in_sizes; (void)n_in; (void)out_size;
    const float* emb  = (const float*)d_in[0];
    const float* W1_0 = (const float*)d_in[2];
    const float* b1_0 = (const float*)d_in[3];
    const float* W2_0 = (const float*)d_in[4];
    const float* b2_0 = (const float*)d_in[5];
    const float* W1_1 = (const float*)d_in[6];
    const float* b1_1 = (const float*)d_in[7];
    const float* W2_1 = (const float*)d_in[8];
    const float* b2_1 = (const float*)d_in[9];
    const float* W1_2 = (const float*)d_in[10];
    const float* b1_2 = (const float*)d_in[11];
    const float* W2_2 = (const float*)d_in[12];
    const float* b2_2 = (const float*)d_in[13];
    const float* W1_3 = (const float*)d_in[14];
    const float* b1_3 = (const float*)d_in[15];
    const float* W2_3 = (const float*)d_in[16];
    const float* b2_3 = (const float*)d_in[17];
    float* out = (float*)d_out;

    static int smem_set = 0;
    if (!smem_set){
        cudaFuncSetAttribute(pair_mma_kernel,
                             cudaFuncAttributeMaxDynamicSharedMemorySize,
                             PAIR_SMEM_BYTES);
        smem_set = 1;
    }

    w2frag_kernel<<<768, 256>>>(W2_1, W2_2, W2_3);
    ab_kernel<<<dim3(4, 32, 6), 256>>>(emb, W1_1, W1_2, W1_3);
    p0_kernel<<<32, 256>>>(emb, W1_0, b1_0, W2_0, b2_0, out);
    pair_mma_kernel<<<dim3(1024, 3), 512, PAIR_SMEM_BYTES>>>(
        emb,
        b1_1, b1_2, b1_3,
        b2_1, b2_2, b2_3,
        out + 262144);
}

// round 4
// speedup vs baseline: 2.9735x; 1.5654x over previous
#include <cuda_runtime.h>

typedef unsigned int U32;
typedef unsigned short U16;

static __device__ __forceinline__ float mish_f(float x){
    // mish(x) = x * ((1+e^x)^2 - 1) / ((1+e^x)^2 + 1), division via
    // bit-hack reciprocal + 2 Newton iterations (FMA pipe, no MUFU.RCP).
    float e  = __expf(fminf(x, 30.0f));
    float u  = 1.0f + e;
    float u2 = u * u;
    float d  = u2 + 1.0f;
    float r  = __int_as_float(0x7EF311C2 - __float_as_int(d));
    r = r * (2.0f - d * r);
    r = r * (2.0f - d * r);
    return x * (u2 - 1.0f) * r;
}

// g_AB: [pred(3)][half(2)][row(2048)][col(256)]  (P = x@W1_top, Q = x@W1_bot)
__device__ float g_AB[6 * 2048 * 256];
// g_W2h: W2 per pred in fp16, pre-laid in m16n8k16 B-fragment uint4 groups:
// halves indexed by [pred][chunk(4)][ks(4)][np(16)][lane(32)][word(4)][comp(2)]
__device__ U16 g_W2h[3 * 65536];

// ---------------------------------------------------------------------------
// w2frag_kernel: W2 -> fp16 fragment layout.
// ---------------------------------------------------------------------------
__global__ __launch_bounds__(256) void w2frag_kernel(
    const float* __restrict__ W2a,
    const float* __restrict__ W2b,
    const float* __restrict__ W2c)
{
    int idx = blockIdx.x * 256 + threadIdx.x;   // 0 .. 196607
    int p = idx >> 16;
    int rem = idx & 65535;
    int k = rem >> 8, n = rem & 255;
    const float* W2 = (p == 0) ? W2a : (p == 1) ? W2b : W2c;
    float v = W2[k * 256 + n];
    U16 hv;
    asm("{ .reg .f16 t; cvt.rn.f16.f32 t, %1; mov.b16 %0, t; }" : "=h"(hv) : "f"(v));
    int c = k >> 6, kk = k & 63;
    int ks = kk >> 4, r = kk & 15;
    int hi = r >> 3, r8 = r & 7, tl = r8 >> 1, comp = r8 & 1;
    int g = n & 7, nt = n >> 3, np = nt >> 1, odd = nt & 1;
    int lane = g * 4 + tl;
    int halfidx = ((((ks * 16 + np) * 32 + lane) * 4) + odd * 2 + hi) * 2 + comp;
    g_W2h[p * 65536 + c * 16384 + halfidx] = hv;
}

// ---------------------------------------------------------------------------
// ab_kernel: P = x @ W1[:128,:], Q = x @ W1[128:,:] for each of 3 predicates.
// ---------------------------------------------------------------------------
__global__ __launch_bounds__(256) void ab_kernel(
    const float* __restrict__ emb,
    const float* __restrict__ W1a,
    const float* __restrict__ W1b,
    const float* __restrict__ W1c)
{
    __shared__ float Xs[16][65];
    __shared__ float Ws[16][64];
    int z = blockIdx.z;
    int p = z >> 1, half = z & 1;
    const float* W = (p == 0 ? W1a : (p == 1 ? W1b : W1c)) + half * 128 * 256;
    int row0 = blockIdx.y * 64;
    int col0 = blockIdx.x * 64;
    int tid = threadIdx.x;
    int tr = tid >> 4, tc = tid & 15;
    float acc[4][4];
    #pragma unroll
    for (int r = 0; r < 4; r++)
        #pragma unroll
        for (int c = 0; c < 4; c++) acc[r][c] = 0.0f;

    for (int k0 = 0; k0 < 128; k0 += 16){
        int kx = tid & 15, rx = tid >> 4;
        #pragma unroll
        for (int pp = 0; pp < 4; pp++)
            Xs[kx][rx + pp*16] = emb[(row0 + rx + pp*16)*128 + k0 + kx];
        int cw = tid & 63, kw = tid >> 6;
        #pragma unroll
        for (int pp = 0; pp < 4; pp++)
            Ws[kw + pp*4][cw] = W[(k0 + kw + pp*4)*256 + col0 + cw];
        __syncthreads();
        #pragma unroll
        for (int k = 0; k < 16; k++){
            float a[4], bv[4];
            #pragma unroll
            for (int r = 0; r < 4; r++) a[r] = Xs[k][tr*4 + r];
            #pragma unroll
            for (int c = 0; c < 4; c++) bv[c] = Ws[k][tc*4 + c];
            #pragma unroll
            for (int r = 0; r < 4; r++)
                #pragma unroll
                for (int c = 0; c < 4; c++)
                    acc[r][c] = fmaf(a[r], bv[c], acc[r][c]);
        }
        __syncthreads();
    }
    float* out = g_AB + (size_t)z * 2048 * 256;
    #pragma unroll
    for (int r = 0; r < 4; r++){
        float4 v = make_float4(acc[r][0], acc[r][1], acc[r][2], acc[r][3]);
        *(float4*)&out[(row0 + tr*4 + r)*256 + col0 + tc*4] = v;
    }
}

// ---------------------------------------------------------------------------
// p0_kernel: arity-1 residual MLP.
// ---------------------------------------------------------------------------
__global__ __launch_bounds__(256) void p0_kernel(
    const float* __restrict__ emb,
    const float* __restrict__ W1,
    const float* __restrict__ b1,
    const float* __restrict__ W2,
    const float* __restrict__ b2,
    float* __restrict__ out)
{
    __shared__ float buf[128][65];
    __shared__ float wch[16][128];
    __shared__ float bias[128];
    int row0 = blockIdx.x * 64;
    int tid = threadIdx.x;
    int tr = tid >> 5, tc = tid & 31;

    for (int idx = tid; idx < 64*128; idx += 256){
        int k = idx & 127, r = idx >> 7;
        buf[k][r] = emb[(row0 + r)*128 + k];
    }
    if (tid < 128) bias[tid] = b1[tid];
    __syncthreads();

    float acc[8][4];
    #pragma unroll
    for (int r = 0; r < 8; r++)
        #pragma unroll
        for (int c = 0; c < 4; c++) acc[r][c] = 0.0f;

    for (int k0 = 0; k0 < 128; k0 += 16){
        #pragma unroll
        for (int pp = 0; pp < 8; pp++){
            int idx = tid + pp*256;
            int c = idx & 127, kk = idx >> 7;
            wch[kk][c] = W1[(k0 + kk)*128 + c];
        }
        __syncthreads();
        #pragma unroll
        for (int k = 0; k < 16; k++){
            float a[8], bv[4];
            #pragma unroll
            for (int r = 0; r < 8; r++) a[r] = buf[k0 + k][tr*8 + r];
            #pragma unroll
            for (int c = 0; c < 4; c++) bv[c] = wch[k][tc*4 + c];
            #pragma unroll
            for (int r = 0; r < 8; r++)
                #pragma unroll
                for (int c = 0; c < 4; c++)
                    acc[r][c] = fmaf(a[r], bv[c], acc[r][c]);
        }
        __syncthreads();
    }

    float hval[8][4];
    #pragma unroll
    for (int r = 0; r < 8; r++)
        #pragma unroll
        for (int c = 0; c < 4; c++)
            hval[r][c] = mish_f(acc[r][c] + bias[tc*4 + c]);
    __syncthreads();
    #pragma unroll
    for (int r = 0; r < 8; r++)
        #pragma unroll
        for (int c = 0; c < 4; c++)
            buf[tc*4 + c][tr*8 + r] = hval[r][c];
    if (tid < 128) bias[tid] = b2[tid];

    float acc2[8][4];
    #pragma unroll
    for (int r = 0; r < 8; r++)
        #pragma unroll
        for (int c = 0; c < 4; c++) acc2[r][c] = 0.0f;

    for (int k0 = 0; k0 < 128; k0 += 16){
        #pragma unroll
        for (int pp = 0; pp < 8; pp++){
            int idx = tid + pp*256;
            int c = idx & 127, kk = idx >> 7;
            wch[kk][c] = W2[(k0 + kk)*128 + c];
        }
        __syncthreads();
        #pragma unroll
        for (int k = 0; k < 16; k++){
            float a[8], bv[4];
            #pragma unroll
            for (int r = 0; r < 8; r++) a[r] = buf[k0 + k][tr*8 + r];
            #pragma unroll
            for (int c = 0; c < 4; c++) bv[c] = wch[k][tc*4 + c];
            #pragma unroll
            for (int r = 0; r < 8; r++)
                #pragma unroll
                for (int c = 0; c < 4; c++)
                    acc2[r][c] = fmaf(a[r], bv[c], acc2[r][c]);
        }
        __syncthreads();
    }

    #pragma unroll
    for (int r = 0; r < 8; r++){
        int row = row0 + tr*8 + r;
        float4 x = *(const float4*)&emb[row*128 + tc*4];
        float4 o = make_float4(x.x + acc2[r][0] + bias[tc*4+0],
                               x.y + acc2[r][1] + bias[tc*4+1],
                               x.z + acc2[r][2] + bias[tc*4+2],
                               x.w + acc2[r][3] + bias[tc*4+3]);
        *(float4*)&out[row*128 + tc*4] = o;
    }
}

// ---------------------------------------------------------------------------
// pair_mma_kernel: arity-2 predicates via fp16 mma.sync (m16n8k16, f32 acc).
// Block = (pred p, batch b, i-pair q): 512 threads, 16 warps (4M x 4N).
// GEMM: M=128 (rows r = isel*64 + j), N=256, K=256 in 4 chunks of 64.
// SMEM bytes: A0[0,16384) B0[16384,49152) A1[49152,65536) B1[65536,98304)
//             av[98304,100352)
// ---------------------------------------------------------------------------
#define PAIR_SMEM_BYTES 100416

#define MMA_F16(d, a, b0v, b1v) \
    asm volatile("mma.sync.aligned.m16n8k16.row.col.f32.f16.f16.f32 " \
        "{%0,%1,%2,%3}, {%4,%5,%6,%7}, {%8,%9}, {%0,%1,%2,%3};" \
        : "+f"(d[0]), "+f"(d[1]), "+f"(d[2]), "+f"(d[3]) \
        : "r"((a).x), "r"((a).y), "r"((a).z), "r"((a).w), \
          "r"(b0v), "r"(b1v))

static __device__ __forceinline__ U32 pack_h2(float lo, float hi){
    U32 r;
    asm("cvt.rn.f16x2.f32 %0, %1, %2;" : "=r"(r) : "f"(hi), "f"(lo));
    return r;
}

static __device__ __forceinline__ void cp16(U32 dst, const void* src){
    asm volatile("cp.async.cg.shared.global [%0], [%1], 16;"
                 :: "r"(dst), "l"(src) : "memory");
}

__global__ __launch_bounds__(512, 1) void pair_mma_kernel(
    const float* __restrict__ emb,
    const float* __restrict__ b1a, const float* __restrict__ b1b, const float* __restrict__ b1c,
    const float* __restrict__ b2a, const float* __restrict__ b2b, const float* __restrict__ b2c,
    float* __restrict__ outbase)
{
    extern __shared__ char smc[];
    float* sm = (float*)smc;
    float* av = (float*)(smc + 98304);
    U32 smem32;
    asm("{ .reg .u64 t; cvta.to.shared.u64 t, %1; cvt.u32.u64 %0, t; }"
        : "=r"(smem32) : "l"(smc));

    int p = blockIdx.y;
    const float* b1 = (p == 0) ? b1a : (p == 1) ? b1b : b1c;
    const float* b2 = (p == 0) ? b2a : (p == 1) ? b2b : b2c;
    float* outp = outbase + (size_t)p * 33554432;

    int bx = blockIdx.x;
    int b = bx >> 5, q = bx & 31;
    const float* Pi0 = g_AB + ((size_t)(p*2) * 2048 + (size_t)(b*64 + 2*q)) * 256;
    const float* Q   = g_AB + ((size_t)(p*2 + 1) * 2048 + (size_t)(b*64)) * 256;
    const uint4* Wsrc = (const uint4*)g_W2h + (size_t)p * 8192;

    int t = threadIdx.x;
    int wid = t >> 5, lane = t & 31;
    int wm = wid & 3, wn = wid >> 2;
    int g = lane >> 2, tl = lane & 3;

    // av[isel][k] = P[i][k] + b1[k]  (Pi1 row is contiguous after Pi0)
    if (t < 256) av[t] = Pi0[t] + b1[t];
    else         av[t] = Pi0[t] + b1[t - 256];
    __syncthreads();

    // producer indices
    int pmt = (t >> 5) & 7;           // m-tile 0..7
    int ksA = t >> 8;                 // 0..1 (handles ks=ksA and ksA+2)
    int isel = pmt >> 2;
    int j0 = (pmt & 3) * 16 + g;
    const float* q0 = Q + (size_t)j0 * 256;
    const float* q1 = q0 + 8 * 256;
    const float* avp = av + isel * 256;

    // W2 chunk async copy: 4 uint4 per thread
    auto produceW = [&](int c, U32 Bs32){
        const uint4* src = Wsrc + c * 2048 + t;
        #pragma unroll
        for (int i = 0; i < 4; i++)
            cp16(Bs32 + (U32)(t + i*512) * 16u, src + i*512);
        asm volatile("cp.async.commit_group;" ::: "memory");
    };

    // A (h) fragments: coalesced STS.128 in exact m16n8k16 A layout
    auto produceA = [&](int c, char* Ab){
        #pragma unroll
        for (int s = 0; s < 2; s++){
            int ks = ksA + 2*s;
            int kb = c*64 + ks*16 + 2*tl;
            float2 qa0 = *(const float2*)(q0 + kb);
            float2 qa1 = *(const float2*)(q0 + kb + 8);
            float2 qb0 = *(const float2*)(q1 + kb);
            float2 qb1 = *(const float2*)(q1 + kb + 8);
            float2 av0 = *(const float2*)(avp + kb);
            float2 av1 = *(const float2*)(avp + kb + 8);
            U32 a0 = pack_h2(mish_f(av0.x + qa0.x), mish_f(av0.y + qa0.y));
            U32 a1 = pack_h2(mish_f(av0.x + qb0.x), mish_f(av0.y + qb0.y));
            U32 a2 = pack_h2(mish_f(av1.x + qa1.x), mish_f(av1.y + qa1.y));
            U32 a3 = pack_h2(mish_f(av1.x + qb1.x), mish_f(av1.y + qb1.y));
            *(uint4*)(Ab + (((ks*8 + pmt)*32 + lane) << 4)) = make_uint4(a0,a1,a2,a3);
        }
    };

    float acc[2][8][4];
    #pragma unroll
    for (int mf = 0; mf < 2; mf++)
        #pragma unroll
        for (int nf = 0; nf < 8; nf++)
            #pragma unroll
            for (int u = 0; u < 4; u++) acc[mf][nf][u] = 0.0f;

    auto consume = [&](char* Ab, char* Bb){
        #pragma unroll
        for (int ks = 0; ks < 4; ks++){
            uint4 aA = *(uint4*)(Ab + (((ks*8 + wm*2    )*32 + lane) << 4));
            uint4 aB = *(uint4*)(Ab + (((ks*8 + wm*2 + 1)*32 + lane) << 4));
            #pragma unroll
            for (int nfp = 0; nfp < 4; nfp++){
                uint4 v = *(uint4*)(Bb + (((ks*16 + wn*4 + nfp)*32 + lane) << 4));
                MMA_F16(acc[0][2*nfp    ], aA, v.x, v.y);
                MMA_F16(acc[1][2*nfp    ], aB, v.x, v.y);
                MMA_F16(acc[0][2*nfp + 1], aA, v.z, v.w);
                MMA_F16(acc[1][2*nfp + 1], aB, v.z, v.w);
            }
        }
    };

    char* A0 = smc;          char* B0 = smc + 16384;
    char* A1 = smc + 49152;  char* B1 = smc + 65536;
    U32 B0a = smem32 + 16384, B1a = smem32 + 65536;

    produceW(0, B0a); produceA(0, A0);
    asm volatile("cp.async.wait_group 0;" ::: "memory");
    __syncthreads();
    produceW(1, B1a); produceA(1, A1); consume(A0, B0);
    asm volatile("cp.async.wait_group 0;" ::: "memory");
    __syncthreads();
    produceW(2, B0a); produceA(2, A0); consume(A1, B1);
    asm volatile("cp.async.wait_group 0;" ::: "memory");
    __syncthreads();
    produceW(3, B1a); produceA(3, A1); consume(A0, B0);
    asm volatile("cp.async.wait_group 0;" ::: "memory");
    __syncthreads();
    consume(A1, B1);
    __syncthreads();

    // ---- epilogue staging: xi0/xi1/b2 -> av region, xj -> front region ----
    float* xi_s = av;                 // [2][128]
    float* b2_s = av + 256;           // [256]
    float* xj_s = sm;                 // [64][132]
    const float* embB = emb + (size_t)(b*64) * 128;

    if (t < 32){
        float4 v = ((const float4*)(embB + (size_t)(2*q)*128))[t];
        *(float4*)&xi_s[t*4] = v;
    } else if (t < 64){
        int t2 = t - 32;
        float4 v = ((const float4*)(embB + (size_t)(2*q + 1)*128))[t2];
        *(float4*)&xi_s[128 + t2*4] = v;
    } else if (t < 128){
        int t2 = t - 64;
        float4 v = ((const float4*)b2)[t2];
        *(float4*)&b2_s[t2*4] = v;
    }
    {
        int jr = t >> 3, seg = t & 7;
        const float4* s = (const float4*)(embB + (size_t)jr*128 + seg*16);
        float4 v0 = s[0], v1 = s[1], v2 = s[2], v3 = s[3];
        float4* d = (float4*)&xj_s[jr*132 + seg*16];
        d[0] = v0; d[1] = v1; d[2] = v2; d[3] = v3;
    }
    __syncthreads();

    int eisel = wm >> 1;
    int i = 2*q + eisel;
    const float* xiw = xi_s + eisel*128;
    size_t rowbase = (size_t)(b*64 + i) * 64;

    #pragma unroll
    for (int mf = 0; mf < 2; mf++){
        int jr0 = (wm & 1)*32 + mf*16 + g;
        int jr1 = jr0 + 8;
        float* o0 = outp + (rowbase + jr0) * 256;
        float* o1 = outp + (rowbase + jr1) * 256;
        #pragma unroll
        for (int nf = 0; nf < 8; nf++){
            int col = wn*64 + nf*8 + 2*tl;
            float add00, add01, add10, add11;
            if (wn < 2){
                float x0 = xiw[col], x1 = xiw[col + 1];
                add00 = x0; add01 = x1; add10 = x0; add11 = x1;
            } else {
                int cc = col - 128;
                add00 = xj_s[jr0*132 + cc];
                add01 = xj_s[jr0*132 + cc + 1];
                add10 = xj_s[jr1*132 + cc];
                add11 = xj_s[jr1*132 + cc + 1];
            }
            float bb0 = b2_s[col], bb1 = b2_s[col + 1];
            float2 v0 = make_float2(acc[mf][nf][0] + add00 + bb0,
                                    acc[mf][nf][1] + add01 + bb1);
            float2 v1 = make_float2(acc[mf][nf][2] + add10 + bb0,
                                    acc[mf][nf][3] + add11 + bb1);
            *(float2*)&o0[col] = v0;
            *(float2*)&o1[col] = v1;
        }
    }
}

// ---------------------------------------------------------------------------
extern "C" void kernel_launch(void* const* d_in, const int* in_sizes, int n_in,
                              void* d_out, int out_size)
{
    (void)in_sizes; (void)n_in; (void)out_size;
    const float* emb  = (const float*)d_in[0];
    const float* W1_0 = (const float*)d_in[2];
    const float* b1_0 = (const float*)d_in[3];
    const float* W2_0 = (const float*)d_in[4];
    const float* b2_0 = (const float*)d_in[5];
    const float* W1_1 = (const float*)d_in[6];
    const float* b1_1 = (const float*)d_in[7];
    const float* W2_1 = (const float*)d_in[8];
    const float* b2_1 = (const float*)d_in[9];
    const float* W1_2 = (const float*)d_in[10];
    const float* b1_2 = (const float*)d_in[11];
    const float* W2_2 = (const float*)d_in[12];
    const float* b2_2 = (const float*)d_in[13];
    const float* W1_3 = (const float*)d_in[14];
    const float* b1_3 = (const float*)d_in[15];
    const float* W2_3 = (const float*)d_in[16];
    const float* b2_3 = (const float*)d_in[17];
    float* out = (float*)d_out;

    static int smem_set = 0;
    if (!smem_set){
        cudaFuncSetAttribute(pair_mma_kernel,
                             cudaFuncAttributeMaxDynamicSharedMemorySize,
                             PAIR_SMEM_BYTES);
        smem_set = 1;
    }

    w2frag_kernel<<<768, 256>>>(W2_1, W2_2, W2_3);
    ab_kernel<<<dim3(4, 32, 6), 256>>>(emb, W1_1, W1_2, W1_3);
    p0_kernel<<<32, 256>>>(emb, W1_0, b1_0, W2_0, b2_0, out);
    pair_mma_kernel<<<dim3(1024, 3), 512, PAIR_SMEM_BYTES>>>(
        emb,
        b1_1, b1_2, b1_3,
        b2_1, b2_2, b2_3,
        out + 262144);
}